// round 4
// baseline (speedup 1.0000x reference)
#include <cuda_runtime.h>
#include <cuda_bf16.h>

// ---------------------------------------------------------------------------
// BiLSTM-CRF forward loss.  B=64, T=512, V=50000, E=256, H=256, L=9.
// embed -> gemm(gx,l0) -> lstm(l0, 8-CTA clusters) -> gemm(gx,l1) -> lstm(l1)
//       -> linear(emissions) -> CRF NLL -> scalar mean.
// ---------------------------------------------------------------------------

#define Bsz  64
#define Tlen 512
#define Emb  256
#define Hd   256
#define Lnum 9
#define BT   (Bsz * Tlen)   // 32768

// -------------------- scratch (device globals; no allocs) -------------------
__device__ float g_x0[(size_t)BT * Emb];            // embedded input
__device__ float g_gx[2ull * BT * 1024];            // per-dir input projections
__device__ float g_y0[(size_t)BT * 512];            // layer0 output [fwd|bwd]
__device__ float g_y1[(size_t)BT * 512];            // layer1 output
__device__ float g_wt0[2 * 256 * 1024];             // w_hh0 re-laid per (rank,k4,col,e)
__device__ float g_wt1[2 * 256 * 1024];             // w_hh1 re-laid
__device__ float g_em[(size_t)BT * Lnum];           // emissions
__device__ float g_partial[Bsz];                    // per-batch (logZ - score)

__device__ __forceinline__ float sigm(float x) { return 1.0f / (1.0f + __expf(-x)); }

__device__ __forceinline__ unsigned smem_u32(const void* p) {
    return (unsigned)__cvta_generic_to_shared(p);
}
__device__ __forceinline__ unsigned mapa_rank(unsigned addr, int rank) {
    unsigned r;
    asm volatile("mapa.shared::cluster.u32 %0, %1, %2;" : "=r"(r) : "r"(addr), "r"(rank));
    return r;
}
__device__ __forceinline__ void st_cluster_f4(unsigned addr, float4 v) {
    asm volatile("st.shared::cluster.v4.f32 [%0], {%1,%2,%3,%4};"
                 :: "r"(addr), "f"(v.x), "f"(v.y), "f"(v.z), "f"(v.w) : "memory");
}
__device__ __forceinline__ void mbar_wait_parity(unsigned addr, int phase) {
    asm volatile(
        "{\n\t.reg .pred P;\n"
        "WL%=:\n\t"
        "mbarrier.try_wait.parity.shared::cta.b64 P, [%0], %1;\n\t"
        "@P bra.uni WD%=;\n\t"
        "bra.uni WL%=;\n"
        "WD%=:\n\t}"
        :: "r"(addr), "r"(phase) : "memory");
}

// -------------------- 1) embedding gather (float4) --------------------------
__global__ void k_embed(const int* __restrict__ ids, const float* __restrict__ emb) {
    int i = blockIdx.x * blockDim.x + threadIdx.x;
    if (i >= BT * (Emb / 4)) return;
    int pos = i >> 6;
    int e4  = i & 63;
    ((float4*)g_x0)[i] = ((const float4*)emb)[(size_t)ids[pos] * (Emb / 4) + e4];
}

// -------- 2) w_hh relayout [2][1024][256] -> [d][rank][k/4][128 cols][4] ----
// gate row = g*256 + r*32 + jj  ->  rank r, col c = g*32+jj
// dst = d*262144 + r*32768 + (k>>2)*512 + c*4 + (k&3)
__global__ void k_trans(const float* __restrict__ w, int layer) {
    int i = blockIdx.x * blockDim.x + threadIdx.x;
    if (i >= 2 * 1024 * 256) return;
    int d   = i >> 18;
    int row = (i >> 8) & 1023;
    int k   = i & 255;
    int g   = row >> 8;
    int r   = (row & 255) >> 5;
    int jj  = row & 31;
    int c   = g * 32 + jj;
    float* dst = layer ? g_wt1 : g_wt0;
    dst[d * 262144 + r * 32768 + (k >> 2) * 512 + c * 4 + (k & 3)] = w[i];
}

// -------------------- 3) gx GEMM: C[d][m][n] = A[m][:] . W[d][n][:] + b[d][n]
__global__ void __launch_bounds__(256) k_gemm(const float* __restrict__ W,
                                              const float* __restrict__ bias,
                                              int layer) {
    __shared__ float As[16][128];
    __shared__ float Ws[16][128];
    const int K = layer ? 512 : 256;
    const float* __restrict__ Ad = layer ? g_y0 : g_x0;
    const int tid = threadIdx.x;
    const int tx = tid & 15, ty = tid >> 4;
    const int m0 = blockIdx.y * 128, n0 = blockIdx.x * 128;
    const int d = blockIdx.z;
    const float* Wd = W + (size_t)d * 1024 * K;
    const float* bd = bias + d * 1024;
    float* Cd = g_gx + (size_t)d * BT * 1024;
    const int lr = tid >> 2;
    const int lc = (tid & 3) * 4;

    float acc[8][8];
#pragma unroll
    for (int i = 0; i < 8; i++)
#pragma unroll
        for (int j = 0; j < 8; j++) acc[i][j] = 0.0f;

    for (int k0 = 0; k0 < K; k0 += 16) {
        float4 a0 = *(const float4*)&Ad[(size_t)(m0 + lr) * K + k0 + lc];
        float4 a1 = *(const float4*)&Ad[(size_t)(m0 + lr + 64) * K + k0 + lc];
        float4 w0 = *(const float4*)&Wd[(size_t)(n0 + lr) * K + k0 + lc];
        float4 w1 = *(const float4*)&Wd[(size_t)(n0 + lr + 64) * K + k0 + lc];
        __syncthreads();
        As[lc + 0][lr] = a0.x; As[lc + 1][lr] = a0.y; As[lc + 2][lr] = a0.z; As[lc + 3][lr] = a0.w;
        As[lc + 0][lr + 64] = a1.x; As[lc + 1][lr + 64] = a1.y; As[lc + 2][lr + 64] = a1.z; As[lc + 3][lr + 64] = a1.w;
        Ws[lc + 0][lr] = w0.x; Ws[lc + 1][lr] = w0.y; Ws[lc + 2][lr] = w0.z; Ws[lc + 3][lr] = w0.w;
        Ws[lc + 0][lr + 64] = w1.x; Ws[lc + 1][lr + 64] = w1.y; Ws[lc + 2][lr + 64] = w1.z; Ws[lc + 3][lr + 64] = w1.w;
        __syncthreads();
#pragma unroll
        for (int kk = 0; kk < 16; kk++) {
            float4 af0 = *(const float4*)&As[kk][ty * 8];
            float4 af1 = *(const float4*)&As[kk][ty * 8 + 4];
            float4 wf0 = *(const float4*)&Ws[kk][tx * 8];
            float4 wf1 = *(const float4*)&Ws[kk][tx * 8 + 4];
            float a[8] = {af0.x, af0.y, af0.z, af0.w, af1.x, af1.y, af1.z, af1.w};
            float w[8] = {wf0.x, wf0.y, wf0.z, wf0.w, wf1.x, wf1.y, wf1.z, wf1.w};
#pragma unroll
            for (int i = 0; i < 8; i++)
#pragma unroll
                for (int j = 0; j < 8; j++) acc[i][j] = fmaf(a[i], w[j], acc[i][j]);
        }
    }
    float bv[8];
#pragma unroll
    for (int j = 0; j < 8; j++) bv[j] = bd[n0 + tx * 8 + j];
#pragma unroll
    for (int i = 0; i < 8; i++) {
        int m = m0 + ty * 8 + i;
        float4 o0 = make_float4(acc[i][0] + bv[0], acc[i][1] + bv[1], acc[i][2] + bv[2], acc[i][3] + bv[3]);
        float4 o1 = make_float4(acc[i][4] + bv[4], acc[i][5] + bv[5], acc[i][6] + bv[6], acc[i][7] + bv[7]);
        *(float4*)&Cd[(size_t)m * 1024 + n0 + tx * 8] = o0;
        *(float4*)&Cd[(size_t)m * 1024 + n0 + tx * 8 + 4] = o1;
    }
}

// -------------------- 4) LSTM recurrence: 8-CTA cluster per (dir, 8-batch) --
// blockIdx.x = cluster*8 + rank.  gid = bx>>3: d = gid>>3, batch base = (gid&7)*8.
// Rank owns 32 hidden units (128 gate cols).  Per step:
//   compute: acc[col][4 batches] = W_slice^T h  (+ gx), col split over 128 thr x 2 bhalf
//   update : 256 thr = (batch 0..7, jj 0..31) gate nonlinearity, c in reg
//   bcast  : h slice -> all 8 ranks' next h buffer via st.shared::cluster
//   barrier: distributed mbarrier (arrive on all ranks, parity wait)
__global__ void __launch_bounds__(256) __cluster_dims__(8, 1, 1)
k_lstm(int layer) {
    __shared__ float hbuf[2][8 * 256];     // double-buffered full h, 8 batches
    __shared__ float gsm[8][128];          // gate slice per batch
    __shared__ float hst[256];             // staged h slice (8 b x 32 jj)
    __shared__ __align__(8) unsigned long long mbar;

    const int tid = threadIdx.x;
    const int r   = blockIdx.x & 7;
    const int gid = blockIdx.x >> 3;
    const int d   = gid >> 3;
    const int b0  = (gid & 7) * 8;
    const float* wt = layer ? g_wt1 : g_wt0;
    float* y = layer ? g_y1 : g_y0;
    const float* gxd = g_gx + (size_t)d * BT * 1024;
    const float4* wf = (const float4*)(wt + d * 262144 + r * 32768);

    const int colh = tid & 127;            // compute-phase gate column
    const int bh   = tid >> 7;             // batch half (0: b0..b3, 1: b4..b7)
    const int ub   = tid >> 5;             // update-phase batch 0..7
    const int ujj  = tid & 31;             // update-phase hidden unit within slice
    const unsigned mbar_addr = smem_u32(&mbar);

    for (int i = tid; i < 2 * 8 * 256; i += 256) ((float*)hbuf)[i] = 0.0f;
    if (tid == 0)
        asm volatile("mbarrier.init.shared.b64 [%0], %1;" :: "r"(mbar_addr), "r"(8) : "memory");
    __syncthreads();
    asm volatile("barrier.cluster.arrive.aligned;\n\tbarrier.cluster.wait.aligned;" ::: "memory");

    // precomputed remote destinations for the h-slice broadcast
    const int cidx = tid & 63;             // float4 index within 256-float slice
    const int crk  = tid >> 6;             // handles ranks crk and crk+4
    const unsigned rel = (unsigned)((cidx >> 3) * 1024 + r * 128 + (cidx & 7) * 16);
    const unsigned a0 = smem_u32(&hbuf[0][0]) + rel;
    const unsigned a1 = smem_u32(&hbuf[1][0]) + rel;
    const unsigned remA_b0 = mapa_rank(a0, crk),     remA_b1 = mapa_rank(a1, crk);
    const unsigned remB_b0 = mapa_rank(a0, crk + 4), remB_b1 = mapa_rank(a1, crk + 4);

    const int gxcol = (colh >> 5) * 256 + r * 32 + (colh & 31);
    float creg = 0.0f;
    int par = 0;

    for (int s = 0; s < Tlen; s++) {
        const int t = d ? (Tlen - 1 - s) : s;
        const int cur = s & 1;
        const float4* hc = (const float4*)&hbuf[cur][0] + (size_t)bh * 4 * 64;

        float acc0 = 0.f, acc1 = 0.f, acc2 = 0.f, acc3 = 0.f;
#pragma unroll 4
        for (int kk = 0; kk < 64; kk++) {
            float4 w4 = wf[kk * 128 + colh];
            float4 h0 = hc[0 * 64 + kk];
            float4 h1 = hc[1 * 64 + kk];
            float4 h2 = hc[2 * 64 + kk];
            float4 h3 = hc[3 * 64 + kk];
            acc0 = fmaf(w4.x, h0.x, acc0); acc0 = fmaf(w4.y, h0.y, acc0);
            acc0 = fmaf(w4.z, h0.z, acc0); acc0 = fmaf(w4.w, h0.w, acc0);
            acc1 = fmaf(w4.x, h1.x, acc1); acc1 = fmaf(w4.y, h1.y, acc1);
            acc1 = fmaf(w4.z, h1.z, acc1); acc1 = fmaf(w4.w, h1.w, acc1);
            acc2 = fmaf(w4.x, h2.x, acc2); acc2 = fmaf(w4.y, h2.y, acc2);
            acc2 = fmaf(w4.z, h2.z, acc2); acc2 = fmaf(w4.w, h2.w, acc2);
            acc3 = fmaf(w4.x, h3.x, acc3); acc3 = fmaf(w4.y, h3.y, acc3);
            acc3 = fmaf(w4.z, h3.z, acc3); acc3 = fmaf(w4.w, h3.w, acc3);
        }
        {
            const size_t gb = ((size_t)(b0 + bh * 4) * Tlen + t) * 1024 + gxcol;
            acc0 += gxd[gb];
            acc1 += gxd[gb + (size_t)Tlen * 1024];
            acc2 += gxd[gb + (size_t)Tlen * 2048];
            acc3 += gxd[gb + (size_t)Tlen * 3072];
        }
        gsm[bh * 4 + 0][colh] = acc0;
        gsm[bh * 4 + 1][colh] = acc1;
        gsm[bh * 4 + 2][colh] = acc2;
        gsm[bh * 4 + 3][colh] = acc3;
        __syncthreads();

        // gate nonlinearity + state update (thread owns (ub, ujj); c in register)
        {
            float gi = gsm[ub][ujj];
            float gf = gsm[ub][32 + ujj];
            float gg = gsm[ub][64 + ujj];
            float go = gsm[ub][96 + ujj];
            creg = sigm(gf) * creg + sigm(gi) * tanhf(gg);
            float h = sigm(go) * tanhf(creg);
            hst[ub * 32 + ujj] = h;
            y[((size_t)(b0 + ub) * Tlen + t) * 512 + d * 256 + r * 32 + ujj] = h;
        }
        __syncthreads();

        // broadcast h slice to all 8 ranks' NEXT buffer
        {
            float4 v = *(const float4*)&hst[cidx * 4];
            if (cur) { st_cluster_f4(remA_b0, v); st_cluster_f4(remB_b0, v); }
            else     { st_cluster_f4(remA_b1, v); st_cluster_f4(remB_b1, v); }
        }
        __syncthreads();

        if (tid == 0) {
            asm volatile("fence.acq_rel.cluster;" ::: "memory");
#pragma unroll
            for (int rk = 0; rk < 8; rk++) {
                unsigned ra = mapa_rank(mbar_addr, rk);
                asm volatile("mbarrier.arrive.shared::cluster.b64 _, [%0];" :: "r"(ra) : "memory");
            }
        }
        mbar_wait_parity(mbar_addr, par);
        asm volatile("fence.acq_rel.cluster;" ::: "memory");
        par ^= 1;
    }
}

// -------------------- 5) emissions = y1 @ lin_w^T + lin_b -------------------
__global__ void __launch_bounds__(256) k_linear(const float* __restrict__ lw,
                                                const float* __restrict__ lb) {
    __shared__ float ws[Lnum * 512];
    __shared__ float bs[Lnum];
    const int tid = threadIdx.x;
    for (int i = tid; i < Lnum * 512; i += 256) ws[i] = lw[i];
    if (tid < Lnum) bs[tid] = lb[tid];
    __syncthreads();
    const int warp = tid >> 5, lane = tid & 31;
    const int pos = blockIdx.x * 8 + warp;
    const float* yp = g_y1 + (size_t)pos * 512;
    float acc[Lnum];
#pragma unroll
    for (int l = 0; l < Lnum; l++) acc[l] = 0.0f;
    for (int k = lane; k < 512; k += 32) {
        float yv = yp[k];
#pragma unroll
        for (int l = 0; l < Lnum; l++) acc[l] = fmaf(yv, ws[l * 512 + k], acc[l]);
    }
#pragma unroll
    for (int l = 0; l < Lnum; l++)
#pragma unroll
        for (int o = 16; o > 0; o >>= 1) acc[l] += __shfl_xor_sync(0xffffffffu, acc[l], o);
    if (lane < Lnum) g_em[(size_t)pos * Lnum + lane] = acc[lane] + bs[lane];
}

// -------------------- 6) CRF NLL: per-batch logZ and gold score -------------
__global__ void k_crf(const int* __restrict__ labels, const int* __restrict__ mask,
                      const float* __restrict__ trans, const float* __restrict__ startt,
                      const float* __restrict__ endt) {
    const int b = blockIdx.x;
    const int lane = threadIdx.x;
    __shared__ float salpha[Lnum];
    const float* em = g_em + (size_t)b * Tlen * Lnum;
    const int* lab = labels + b * Tlen;
    const int* msk = mask + b * Tlen;
    const int j = (lane < Lnum) ? lane : 0;

    float tr[Lnum];
#pragma unroll
    for (int i = 0; i < Lnum; i++) tr[i] = trans[i * Lnum + j];

    int mcount = 0;
    for (int t = lane; t < Tlen; t += 32) mcount += msk[t];
#pragma unroll
    for (int o = 16; o > 0; o >>= 1) mcount += __shfl_xor_sync(0xffffffffu, mcount, o);
    float sc = 0.0f;
    for (int t = lane + 1; t < Tlen; t += 32)
        if (msk[t]) sc += trans[lab[t - 1] * Lnum + lab[t]] + em[t * Lnum + lab[t]];
#pragma unroll
    for (int o = 16; o > 0; o >>= 1) sc += __shfl_xor_sync(0xffffffffu, sc, o);

    float alpha = startt[j] + em[j];
    for (int t = 1; t < Tlen; t++) {
        if (lane < Lnum) salpha[lane] = alpha;
        __syncwarp();
        float vs[Lnum];
        float m = -1e30f;
#pragma unroll
        for (int i = 0; i < Lnum; i++) {
            vs[i] = salpha[i] + tr[i];
            m = fmaxf(m, vs[i]);
        }
        float ssum = 0.0f;
#pragma unroll
        for (int i = 0; i < Lnum; i++) ssum += __expf(vs[i] - m);
        float na = m + __logf(ssum) + em[t * Lnum + j];
        if (msk[t]) alpha = na;
        __syncwarp();
    }
    float v = (lane < Lnum) ? alpha + endt[lane] : -1e30f;
    float mm = v;
#pragma unroll
    for (int o = 16; o > 0; o >>= 1) mm = fmaxf(mm, __shfl_xor_sync(0xffffffffu, mm, o));
    float e = (lane < Lnum) ? __expf(v - mm) : 0.0f;
#pragma unroll
    for (int o = 16; o > 0; o >>= 1) e += __shfl_xor_sync(0xffffffffu, e, o);
    float logZ = mm + __logf(e);

    if (lane == 0) {
        sc += startt[lab[0]] + em[lab[0]] + endt[lab[mcount - 1]];
        g_partial[b] = logZ - sc;
    }
}

// -------------------- 7) mean reduce -> scalar loss --------------------------
__global__ void k_final(float* __restrict__ out) {
    __shared__ float s[Bsz];
    const int tid = threadIdx.x;
    s[tid] = g_partial[tid];
    __syncthreads();
    for (int o = 32; o > 0; o >>= 1) {
        if (tid < o) s[tid] += s[tid + o];
        __syncthreads();
    }
    if (tid == 0) out[0] = s[0] * (1.0f / (float)Bsz);
}

// ---------------------------------------------------------------------------
extern "C" void kernel_launch(void* const* d_in, const int* in_sizes, int n_in,
                              void* d_out, int out_size) {
    (void)in_sizes; (void)n_in; (void)out_size;
    const int*   input_ids = (const int*)d_in[0];
    const int*   attn      = (const int*)d_in[1];
    const int*   labels    = (const int*)d_in[2];
    const float* emb       = (const float*)d_in[3];
    const float* w_ih0     = (const float*)d_in[4];
    const float* w_hh0     = (const float*)d_in[5];
    const float* b0        = (const float*)d_in[6];
    const float* w_ih1     = (const float*)d_in[7];
    const float* w_hh1     = (const float*)d_in[8];
    const float* b1        = (const float*)d_in[9];
    const float* lin_w     = (const float*)d_in[10];
    const float* lin_b     = (const float*)d_in[11];
    const float* trans     = (const float*)d_in[12];
    const float* startt    = (const float*)d_in[13];
    const float* endt      = (const float*)d_in[14];
    float* out = (float*)d_out;

    k_embed<<<(BT * (Emb / 4) + 255) / 256, 256>>>(input_ids, emb);
    k_trans<<<(2 * 1024 * 256 + 255) / 256, 256>>>(w_hh0, 0);
    k_trans<<<(2 * 1024 * 256 + 255) / 256, 256>>>(w_hh1, 1);

    k_gemm<<<dim3(8, 256, 2), 256>>>(w_ih0, b0, 0);
    k_lstm<<<128, 256>>>(0);

    k_gemm<<<dim3(8, 256, 2), 256>>>(w_ih1, b1, 1);
    k_lstm<<<128, 256>>>(1);

    k_linear<<<BT / 8, 256>>>(lin_w, lin_b);
    k_crf<<<Bsz, 32>>>(labels, attn, trans, startt, endt);
    k_final<<<1, 64>>>(out);
}

// round 6
// speedup vs baseline: 1.5043x; 1.5043x over previous
#include <cuda_runtime.h>
#include <cuda_bf16.h>

// ---------------------------------------------------------------------------
// BiLSTM-CRF forward loss.  B=64, T=512, V=50000, E=256, H=256, L=9.
// embed -> gemm(gx,l0) -> lstm(l0, 8-CTA clusters, SMEM-resident W, f32x2)
//       -> gemm(gx,l1) -> lstm(l1) -> linear -> CRF NLL -> mean.
// ---------------------------------------------------------------------------

#define Bsz  64
#define Tlen 512
#define Emb  256
#define Hd   256
#define Lnum 9
#define BT   (Bsz * Tlen)   // 32768

// dynamic smem layout for k_lstm (float offsets)
#define SM_W    0          // [32768]  w slice (rank): [k/4][128 cols][4]
#define SM_H    32768      // [2][256][8]  double-buffered h, k-major batch-minor
#define SM_G    36864      // [8][128] gate slice per batch
#define SM_HST  37888      // [256] staged h slice (32 units x 8 batches)
#define SM_MBAR 38144      // u64 mbarrier
#define SM_BYTES ((SM_MBAR + 4) * 4)

// -------------------- scratch (device globals; no allocs) -------------------
__device__ float g_x0[(size_t)BT * Emb];
__device__ float g_gx[2ull * BT * 1024];
__device__ float g_y0[(size_t)BT * 512];
__device__ float g_y1[(size_t)BT * 512];
__device__ float g_wt0[2 * 256 * 1024];
__device__ float g_wt1[2 * 256 * 1024];
__device__ float g_em[(size_t)BT * Lnum];
__device__ float g_partial[Bsz];

__device__ __forceinline__ float sigm(float x) { return 1.0f / (1.0f + __expf(-x)); }

__device__ __forceinline__ unsigned smem_u32(const void* p) {
    return (unsigned)__cvta_generic_to_shared(p);
}
__device__ __forceinline__ unsigned mapa_rank(unsigned addr, int rank) {
    unsigned r;
    asm volatile("mapa.shared::cluster.u32 %0, %1, %2;" : "=r"(r) : "r"(addr), "r"(rank));
    return r;
}
__device__ __forceinline__ void st_cluster_f4(unsigned addr, float4 v) {
    asm volatile("st.shared::cluster.v4.f32 [%0], {%1,%2,%3,%4};"
                 :: "r"(addr), "f"(v.x), "f"(v.y), "f"(v.z), "f"(v.w) : "memory");
}
__device__ __forceinline__ void mbar_wait_parity(unsigned addr, int phase) {
    asm volatile(
        "{\n\t.reg .pred P;\n"
        "WL%=:\n\t"
        "mbarrier.try_wait.parity.shared::cta.b64 P, [%0], %1;\n\t"
        "@P bra.uni WD%=;\n\t"
        "bra.uni WL%=;\n"
        "WD%=:\n\t}"
        :: "r"(addr), "r"(phase) : "memory");
}
__device__ __forceinline__ void fma2(unsigned long long& acc,
                                     unsigned long long a, unsigned long long b) {
    asm("fma.rn.f32x2 %0, %1, %2, %0;" : "+l"(acc) : "l"(a), "l"(b));
}
__device__ __forceinline__ unsigned long long pack2(float f) {
    unsigned long long r;
    asm("mov.b64 %0, {%1, %1};" : "=l"(r) : "f"(f));
    return r;
}

// -------------------- 1) embedding gather (float4) --------------------------
__global__ void k_embed(const int* __restrict__ ids, const float* __restrict__ emb) {
    int i = blockIdx.x * blockDim.x + threadIdx.x;
    if (i >= BT * (Emb / 4)) return;
    int pos = i >> 6;
    int e4  = i & 63;
    ((float4*)g_x0)[i] = ((const float4*)emb)[(size_t)ids[pos] * (Emb / 4) + e4];
}

// -------- 2) w_hh relayout [2][1024][256] -> [d][rank][k/4][128 cols][4] ----
__global__ void k_trans(const float* __restrict__ w, int layer) {
    int i = blockIdx.x * blockDim.x + threadIdx.x;
    if (i >= 2 * 1024 * 256) return;
    int d   = i >> 18;
    int row = (i >> 8) & 1023;
    int k   = i & 255;
    int g   = row >> 8;
    int r   = (row & 255) >> 5;
    int jj  = row & 31;
    int c   = g * 32 + jj;
    float* dst = layer ? g_wt1 : g_wt0;
    dst[d * 262144 + r * 32768 + (k >> 2) * 512 + c * 4 + (k & 3)] = w[i];
}

// -------------------- 3) gx GEMM (fp32 SIMT) ---------------------------------
__global__ void __launch_bounds__(256) k_gemm(const float* __restrict__ W,
                                              const float* __restrict__ bias,
                                              int layer) {
    __shared__ float As[16][128];
    __shared__ float Ws[16][128];
    const int K = layer ? 512 : 256;
    const float* __restrict__ Ad = layer ? g_y0 : g_x0;
    const int tid = threadIdx.x;
    const int tx = tid & 15, ty = tid >> 4;
    const int m0 = blockIdx.y * 128, n0 = blockIdx.x * 128;
    const int d = blockIdx.z;
    const float* Wd = W + (size_t)d * 1024 * K;
    const float* bd = bias + d * 1024;
    float* Cd = g_gx + (size_t)d * BT * 1024;
    const int lr = tid >> 2;
    const int lc = (tid & 3) * 4;

    float acc[8][8];
#pragma unroll
    for (int i = 0; i < 8; i++)
#pragma unroll
        for (int j = 0; j < 8; j++) acc[i][j] = 0.0f;

    for (int k0 = 0; k0 < K; k0 += 16) {
        float4 a0 = *(const float4*)&Ad[(size_t)(m0 + lr) * K + k0 + lc];
        float4 a1 = *(const float4*)&Ad[(size_t)(m0 + lr + 64) * K + k0 + lc];
        float4 w0 = *(const float4*)&Wd[(size_t)(n0 + lr) * K + k0 + lc];
        float4 w1 = *(const float4*)&Wd[(size_t)(n0 + lr + 64) * K + k0 + lc];
        __syncthreads();
        As[lc + 0][lr] = a0.x; As[lc + 1][lr] = a0.y; As[lc + 2][lr] = a0.z; As[lc + 3][lr] = a0.w;
        As[lc + 0][lr + 64] = a1.x; As[lc + 1][lr + 64] = a1.y; As[lc + 2][lr + 64] = a1.z; As[lc + 3][lr + 64] = a1.w;
        Ws[lc + 0][lr] = w0.x; Ws[lc + 1][lr] = w0.y; Ws[lc + 2][lr] = w0.z; Ws[lc + 3][lr] = w0.w;
        Ws[lc + 0][lr + 64] = w1.x; Ws[lc + 1][lr + 64] = w1.y; Ws[lc + 2][lr + 64] = w1.z; Ws[lc + 3][lr + 64] = w1.w;
        __syncthreads();
#pragma unroll
        for (int kk = 0; kk < 16; kk++) {
            float4 af0 = *(const float4*)&As[kk][ty * 8];
            float4 af1 = *(const float4*)&As[kk][ty * 8 + 4];
            float4 wf0 = *(const float4*)&Ws[kk][tx * 8];
            float4 wf1 = *(const float4*)&Ws[kk][tx * 8 + 4];
            float a[8] = {af0.x, af0.y, af0.z, af0.w, af1.x, af1.y, af1.z, af1.w};
            float w[8] = {wf0.x, wf0.y, wf0.z, wf0.w, wf1.x, wf1.y, wf1.z, wf1.w};
#pragma unroll
            for (int i = 0; i < 8; i++)
#pragma unroll
                for (int j = 0; j < 8; j++) acc[i][j] = fmaf(a[i], w[j], acc[i][j]);
        }
    }
    float bv[8];
#pragma unroll
    for (int j = 0; j < 8; j++) bv[j] = bd[n0 + tx * 8 + j];
#pragma unroll
    for (int i = 0; i < 8; i++) {
        int m = m0 + ty * 8 + i;
        float4 o0 = make_float4(acc[i][0] + bv[0], acc[i][1] + bv[1], acc[i][2] + bv[2], acc[i][3] + bv[3]);
        float4 o1 = make_float4(acc[i][4] + bv[4], acc[i][5] + bv[5], acc[i][6] + bv[6], acc[i][7] + bv[7]);
        *(float4*)&Cd[(size_t)m * 1024 + n0 + tx * 8] = o0;
        *(float4*)&Cd[(size_t)m * 1024 + n0 + tx * 8 + 4] = o1;
    }
}

// -------------------- 4) LSTM recurrence: 8-CTA cluster, SMEM weights -------
// blockIdx.x = cluster*8 + rank.  gid = bx>>3: d = gid>>3, batch base (gid&7)*8.
// Rank owns 32 hidden units = 128 gate cols.  W slice (128 KB) loaded to SMEM
// once.  h stored [k][8 batches] so batch pairs load as ulonglong2 for f32x2.
// Sync per step: R3-proven fence.acq_rel.cluster + tid0 remote arrives +
// parity wait.  Final cluster barrier after the loop so no CTA exits while
// peers' remote stores into its SMEM are in flight.
__global__ void __launch_bounds__(256) __cluster_dims__(8, 1, 1)
k_lstm(int layer) {
    extern __shared__ float sm[];
    float* wsm = sm + SM_W;
    float* hb  = sm + SM_H;        // [2][256][8]
    float* gsm = sm + SM_G;        // [8][128]
    float* hst = sm + SM_HST;      // [256]
    unsigned long long* mbar = (unsigned long long*)(sm + SM_MBAR);

    const int tid = threadIdx.x;
    const int r   = blockIdx.x & 7;
    const int gid = blockIdx.x >> 3;
    const int d   = gid >> 3;
    const int b0  = (gid & 7) * 8;
    const float* wt = layer ? g_wt1 : g_wt0;
    float* y = layer ? g_y1 : g_y0;
    const float* gxd = g_gx + (size_t)d * BT * 1024;
    const unsigned mbar_addr = smem_u32(mbar);

    // load W slice into smem (float4), zero h buffers
    {
        const float4* src = (const float4*)(wt + d * 262144 + r * 32768);
        float4* dst = (float4*)wsm;
        for (int i = tid; i < 8192; i += 256) dst[i] = src[i];
        for (int i = tid; i < 2 * 256 * 8; i += 256) hb[i] = 0.0f;
    }
    if (tid == 0)
        asm volatile("mbarrier.init.shared.b64 [%0], %1;" :: "r"(mbar_addr), "r"(8) : "memory");
    __syncthreads();
    asm volatile("barrier.cluster.arrive.aligned;\n\tbarrier.cluster.wait.aligned;" ::: "memory");

    const int col = tid & 127;     // gate column within rank slice
    const int bp  = tid >> 7;      // batch half: 0 -> b0..b3, 1 -> b4..b7
    const int ub  = tid >> 5;      // update-phase batch
    const int ujj = tid & 31;      // update-phase unit within slice

    // broadcast destinations: thread covers (cidx, ranks crk & crk+4)
    const int cidx = tid & 63;     // float4 index within 256-float hst
    const int crk  = tid >> 6;
    const unsigned rel = (unsigned)(((r * 32 + (cidx >> 1)) * 8 + (cidx & 1) * 4) * 4);
    const unsigned hb_b0 = smem_u32(hb) + rel;
    const unsigned hb_b1 = hb_b0 + 8192;
    const unsigned remA_b0 = mapa_rank(hb_b0, crk),     remA_b1 = mapa_rank(hb_b1, crk);
    const unsigned remB_b0 = mapa_rank(hb_b0, crk + 4), remB_b1 = mapa_rank(hb_b1, crk + 4);

    const int gxcol = (col >> 5) * 256 + r * 32 + (col & 31);
    const float4* wsm4 = (const float4*)wsm;
    float creg = 0.0f;
    int par = 0;

    for (int s = 0; s < Tlen; s++) {
        const int t = d ? (Tlen - 1 - s) : s;
        const int cur = s & 1;

        // gx prefetch (independent of FMA loop; hides DRAM latency)
        const size_t gb = ((size_t)(b0 + bp * 4) * Tlen + t) * 1024 + gxcol;
        float gx0 = gxd[gb];
        float gx1 = gxd[gb + (size_t)Tlen * 1024];
        float gx2 = gxd[gb + (size_t)Tlen * 2048];
        float gx3 = gxd[gb + (size_t)Tlen * 3072];

        unsigned long long acc01 = 0ull, acc23 = 0ull;
        const float* hc = hb + cur * 2048 + bp * 4;
#pragma unroll 4
        for (int kk = 0; kk < 64; kk++) {
            float4 w4 = wsm4[kk * 128 + col];
            const float* hrow = hc + kk * 32;
            ulonglong2 h0 = *(const ulonglong2*)(hrow);
            ulonglong2 h1 = *(const ulonglong2*)(hrow + 8);
            ulonglong2 h2 = *(const ulonglong2*)(hrow + 16);
            ulonglong2 h3 = *(const ulonglong2*)(hrow + 24);
            unsigned long long w0 = pack2(w4.x);
            unsigned long long w1 = pack2(w4.y);
            unsigned long long w2 = pack2(w4.z);
            unsigned long long w3 = pack2(w4.w);
            fma2(acc01, w0, h0.x); fma2(acc23, w0, h0.y);
            fma2(acc01, w1, h1.x); fma2(acc23, w1, h1.y);
            fma2(acc01, w2, h2.x); fma2(acc23, w2, h2.y);
            fma2(acc01, w3, h3.x); fma2(acc23, w3, h3.y);
        }
        {
            float a0, a1, a2, a3;
            asm("mov.b64 {%0,%1}, %2;" : "=f"(a0), "=f"(a1) : "l"(acc01));
            asm("mov.b64 {%0,%1}, %2;" : "=f"(a2), "=f"(a3) : "l"(acc23));
            gsm[(bp * 4 + 0) * 128 + col] = a0 + gx0;
            gsm[(bp * 4 + 1) * 128 + col] = a1 + gx1;
            gsm[(bp * 4 + 2) * 128 + col] = a2 + gx2;
            gsm[(bp * 4 + 3) * 128 + col] = a3 + gx3;
        }
        __syncthreads();

        // gate nonlinearity + state update; thread owns (ub, ujj), c in reg
        {
            float gi = gsm[ub * 128 + ujj];
            float gf = gsm[ub * 128 + 32 + ujj];
            float gg = gsm[ub * 128 + 64 + ujj];
            float go = gsm[ub * 128 + 96 + ujj];
            creg = sigm(gf) * creg + sigm(gi) * tanhf(gg);
            float h = sigm(go) * tanhf(creg);
            hst[ujj * 8 + ub] = h;
            y[((size_t)(b0 + ub) * Tlen + t) * 512 + d * 256 + r * 32 + ujj] = h;
        }
        __syncthreads();

        // broadcast h slice into every rank's NEXT h buffer
        {
            float4 v = *(const float4*)&hst[cidx * 4];
            if (cur) { st_cluster_f4(remA_b0, v); st_cluster_f4(remB_b0, v); }
            else     { st_cluster_f4(remA_b1, v); st_cluster_f4(remB_b1, v); }
        }
        __syncthreads();

        // R3-proven inter-rank step barrier (runs on EVERY step, incl. last)
        if (tid == 0) {
            asm volatile("fence.acq_rel.cluster;" ::: "memory");
#pragma unroll
            for (int rk = 0; rk < 8; rk++) {
                unsigned ra = mapa_rank(mbar_addr, rk);
                asm volatile("mbarrier.arrive.shared::cluster.b64 _, [%0];" :: "r"(ra) : "memory");
            }
        }
        mbar_wait_parity(mbar_addr, par);
        asm volatile("fence.acq_rel.cluster;" ::: "memory");
        par ^= 1;
    }

    // no CTA may exit while peers' remote stores into its SMEM are in flight
    asm volatile("barrier.cluster.arrive.aligned;\n\tbarrier.cluster.wait.aligned;" ::: "memory");
}

// -------------------- 5) emissions = y1 @ lin_w^T + lin_b -------------------
__global__ void __launch_bounds__(256) k_linear(const float* __restrict__ lw,
                                                const float* __restrict__ lb) {
    __shared__ float ws[Lnum * 512];
    __shared__ float bs[Lnum];
    const int tid = threadIdx.x;
    for (int i = tid; i < Lnum * 512; i += 256) ws[i] = lw[i];
    if (tid < Lnum) bs[tid] = lb[tid];
    __syncthreads();
    const int warp = tid >> 5, lane = tid & 31;
    const int pos = blockIdx.x * 8 + warp;
    const float* yp = g_y1 + (size_t)pos * 512;
    float acc[Lnum];
#pragma unroll
    for (int l = 0; l < Lnum; l++) acc[l] = 0.0f;
    for (int k = lane; k < 512; k += 32) {
        float yv = yp[k];
#pragma unroll
        for (int l = 0; l < Lnum; l++) acc[l] = fmaf(yv, ws[l * 512 + k], acc[l]);
    }
#pragma unroll
    for (int l = 0; l < Lnum; l++)
#pragma unroll
        for (int o = 16; o > 0; o >>= 1) acc[l] += __shfl_xor_sync(0xffffffffu, acc[l], o);
    if (lane < Lnum) g_em[(size_t)pos * Lnum + lane] = acc[lane] + bs[lane];
}

// -------------------- 6) CRF NLL --------------------------------------------
__global__ void k_crf(const int* __restrict__ labels, const int* __restrict__ mask,
                      const float* __restrict__ trans, const float* __restrict__ startt,
                      const float* __restrict__ endt) {
    const int b = blockIdx.x;
    const int lane = threadIdx.x;
    __shared__ float salpha[Lnum];
    const float* em = g_em + (size_t)b * Tlen * Lnum;
    const int* lab = labels + b * Tlen;
    const int* msk = mask + b * Tlen;
    const int j = (lane < Lnum) ? lane : 0;

    float tr[Lnum];
#pragma unroll
    for (int i = 0; i < Lnum; i++) tr[i] = trans[i * Lnum + j];

    int mcount = 0;
    for (int t = lane; t < Tlen; t += 32) mcount += msk[t];
#pragma unroll
    for (int o = 16; o > 0; o >>= 1) mcount += __shfl_xor_sync(0xffffffffu, mcount, o);
    float sc = 0.0f;
    for (int t = lane + 1; t < Tlen; t += 32)
        if (msk[t]) sc += trans[lab[t - 1] * Lnum + lab[t]] + em[t * Lnum + lab[t]];
#pragma unroll
    for (int o = 16; o > 0; o >>= 1) sc += __shfl_xor_sync(0xffffffffu, sc, o);

    float alpha = startt[j] + em[j];
    for (int t = 1; t < Tlen; t++) {
        if (lane < Lnum) salpha[lane] = alpha;
        __syncwarp();
        float vs[Lnum];
        float m = -1e30f;
#pragma unroll
        for (int i = 0; i < Lnum; i++) {
            vs[i] = salpha[i] + tr[i];
            m = fmaxf(m, vs[i]);
        }
        float ssum = 0.0f;
#pragma unroll
        for (int i = 0; i < Lnum; i++) ssum += __expf(vs[i] - m);
        float na = m + __logf(ssum) + em[t * Lnum + j];
        if (msk[t]) alpha = na;
        __syncwarp();
    }
    float v = (lane < Lnum) ? alpha + endt[lane] : -1e30f;
    float mm = v;
#pragma unroll
    for (int o = 16; o > 0; o >>= 1) mm = fmaxf(mm, __shfl_xor_sync(0xffffffffu, mm, o));
    float e = (lane < Lnum) ? __expf(v - mm) : 0.0f;
#pragma unroll
    for (int o = 16; o > 0; o >>= 1) e += __shfl_xor_sync(0xffffffffu, e, o);
    float logZ = mm + __logf(e);

    if (lane == 0) {
        sc += startt[lab[0]] + em[lab[0]] + endt[lab[mcount - 1]];
        g_partial[b] = logZ - sc;
    }
}

// -------------------- 7) mean reduce ----------------------------------------
__global__ void k_final(float* __restrict__ out) {
    __shared__ float s[Bsz];
    const int tid = threadIdx.x;
    s[tid] = g_partial[tid];
    __syncthreads();
    for (int o = 32; o > 0; o >>= 1) {
        if (tid < o) s[tid] += s[tid + o];
        __syncthreads();
    }
    if (tid == 0) out[0] = s[0] * (1.0f / (float)Bsz);
}

// ---------------------------------------------------------------------------
extern "C" void kernel_launch(void* const* d_in, const int* in_sizes, int n_in,
                              void* d_out, int out_size) {
    (void)in_sizes; (void)n_in; (void)out_size;
    const int*   input_ids = (const int*)d_in[0];
    const int*   attn      = (const int*)d_in[1];
    const int*   labels    = (const int*)d_in[2];
    const float* emb       = (const float*)d_in[3];
    const float* w_ih0     = (const float*)d_in[4];
    const float* w_hh0     = (const float*)d_in[5];
    const float* b0        = (const float*)d_in[6];
    const float* w_ih1     = (const float*)d_in[7];
    const float* w_hh1     = (const float*)d_in[8];
    const float* b1        = (const float*)d_in[9];
    const float* lin_w     = (const float*)d_in[10];
    const float* lin_b     = (const float*)d_in[11];
    const float* trans     = (const float*)d_in[12];
    const float* startt    = (const float*)d_in[13];
    const float* endt      = (const float*)d_in[14];
    float* out = (float*)d_out;

    // deterministic, capture-legal, idempotent — no static guard
    cudaFuncSetAttribute(k_lstm, cudaFuncAttributeMaxDynamicSharedMemorySize, SM_BYTES);

    k_embed<<<(BT * (Emb / 4) + 255) / 256, 256>>>(input_ids, emb);
    k_trans<<<(2 * 1024 * 256 + 255) / 256, 256>>>(w_hh0, 0);
    k_trans<<<(2 * 1024 * 256 + 255) / 256, 256>>>(w_hh1, 1);

    k_gemm<<<dim3(8, 256, 2), 256>>>(w_ih0, b0, 0);
    k_lstm<<<128, 256, SM_BYTES>>>(0);

    k_gemm<<<dim3(8, 256, 2), 256>>>(w_ih1, b1, 1);
    k_lstm<<<128, 256, SM_BYTES>>>(1);

    k_linear<<<BT / 8, 256>>>(lin_w, lin_b);
    k_crf<<<Bsz, 32>>>(labels, attn, trans, startt, endt);
    k_final<<<1, 64>>>(out);
}